// round 17
// speedup vs baseline: 4.4975x; 1.0298x over previous
#include <cuda_runtime.h>
#include <cuda_fp16.h>
#include <math.h>
#include <stdint.h>

namespace {

typedef __half f16;

constexpr int NT  = 8192;   // tokens
constexpr int D   = 1024;   // model dim
constexpr int H   = 8;      // heads
constexpr int DHd = 64;     // dim head
constexpr int IN  = 512;    // h*dh
constexpr int LM  = 256;    // landmarks
constexpr int WQ  = 256;    // wq/wk dim
constexpr int CK  = 33;     // conv kernel

// ---------------- scratch (device globals; no runtime alloc) ----------------
__device__ __align__(16) float g_Qh  [H * NT * DHd];
__device__ __align__(16) float g_Kh  [H * NT * DHd];
__device__ __align__(16) float g_Vh  [H * NT * DHd];
__device__ __align__(16) float g_attn1[H * NT * LM];
__device__ __align__(16) float g_attn3[H * LM * NT];
__device__ __align__(16) float g_attn2[H * LM * LM];
__device__ __align__(16) float g_xz  [H * LM * LM];
__device__ __align__(16) float g_t1  [H * LM * LM];
__device__ __align__(16) float g_t2  [H * LM * LM];
__device__ __align__(16) float g_z   [H * LM * LM];
__device__ __align__(16) float g_z2  [H * LM * LM];
__device__ __align__(16) float g_t3vp[H * 8 * LM * DHd];
__device__ __align__(16) float g_t3v [H * LM * DHd];
__device__ __align__(16) float g_t2v [H * LM * DHd];
__device__ __align__(16) float g_conv[NT * IN];
__device__ __align__(16) float g_OH  [NT * IN];
__device__ __align__(16) float g_enc [NT * D];
__device__ __align__(16) float g_q2k2[NT * 2 * WQ];
__device__ __align__(16) float g_val [NT * D];
__device__ __align__(16) float g_Araw[NT];
__device__ __align__(16) float g_alpha[NT];
__device__ __align__(16) float g_max2[2];

// fp16 A-split (hi/lo) buffers
__device__ __align__(16) f16 g_dense_h[NT * D];
__device__ __align__(16) f16 g_dense_l[NT * D];
__device__ __align__(16) f16 g_enc_h  [NT * D];
__device__ __align__(16) f16 g_enc_l  [NT * D];
__device__ __align__(16) f16 g_OH_h   [NT * IN];
__device__ __align__(16) f16 g_OH_l   [NT * IN];
// fp16 B-single (transposed [N][K]) buffers
__device__ __align__(16) f16 g_wqkvT[3 * IN * D];
__device__ __align__(16) f16 g_wvT  [D * D];
__device__ __align__(16) f16 g_woutT[D * IN];
__device__ __align__(16) f16 g_wqkT [2 * WQ * D];
// heads
__device__ __align__(16) f16 g_Qh_h[H * NT * DHd];
__device__ __align__(16) f16 g_Qh_l[H * NT * DHd];
__device__ __align__(16) f16 g_KhB [H * NT * DHd];   // B single
__device__ __align__(16) f16 g_VhT [H * DHd * NT];   // B single, transposed
__device__ __align__(16) f16 g_qlm_h[H * LM * DHd];
__device__ __align__(16) f16 g_qlm_l[H * LM * DHd];
__device__ __align__(16) f16 g_klm [H * LM * DHd];   // B single
// attention prob splits (A operands)
__device__ __align__(16) f16 g_a1h[H * NT * LM];
__device__ __align__(16) f16 g_a1l[H * NT * LM];
__device__ __align__(16) f16 g_a3h[H * LM * NT];
__device__ __align__(16) f16 g_a3l[H * LM * NT];
__device__ __align__(16) f16 g_a2h[H * LM * LM];
__device__ __align__(16) f16 g_a2l[H * LM * LM];
// pinv buffers
__device__ __align__(16) f16 g_zh_a [H * LM * LM];
__device__ __align__(16) f16 g_zl_a [H * LM * LM];
__device__ __align__(16) f16 g_zT_a [H * LM * LM];
__device__ __align__(16) f16 g_zh_b [H * LM * LM];
__device__ __align__(16) f16 g_zl_b [H * LM * LM];
__device__ __align__(16) f16 g_zT_b [H * LM * LM];
__device__ __align__(16) f16 g_xzh [H * LM * LM];
__device__ __align__(16) f16 g_xzl [H * LM * LM];
__device__ __align__(16) f16 g_xzT [H * LM * LM];
__device__ __align__(16) f16 g_t2T [H * LM * LM];
__device__ __align__(16) f16 g_t1T [H * LM * LM];
__device__ __align__(16) f16 g_t2vT[H * DHd * LM];

// ================= helpers =================
__device__ __forceinline__ uint32_t smem_u32(const void* p) {
    uint32_t a;
    asm("{ .reg .u64 t; cvta.to.shared.u64 t, %1; cvt.u32.u64 %0, t; }" : "=r"(a) : "l"(p));
    return a;
}
__device__ __forceinline__ void cpasync16(uint32_t dst, const void* src) {
    asm volatile("cp.async.cg.shared.global [%0], [%1], 16;" :: "r"(dst), "l"(src));
}
__device__ __forceinline__ void cp_commit() { asm volatile("cp.async.commit_group;"); }
__device__ __forceinline__ void ldsm4(uint32_t (&r)[4], uint32_t addr) {
    asm volatile("ldmatrix.sync.aligned.m8n8.x4.shared.b16 {%0,%1,%2,%3}, [%4];"
        : "=r"(r[0]), "=r"(r[1]), "=r"(r[2]), "=r"(r[3]) : "r"(addr));
}
__device__ __forceinline__ void mma16816(float (&d)[4], const uint32_t (&a)[4],
                                         uint32_t b0, uint32_t b1) {
    asm volatile(
        "mma.sync.aligned.m16n8k16.row.col.f32.f16.f16.f32 "
        "{%0,%1,%2,%3}, {%4,%5,%6,%7}, {%8,%9}, {%0,%1,%2,%3};"
        : "+f"(d[0]), "+f"(d[1]), "+f"(d[2]), "+f"(d[3])
        : "r"(a[0]), "r"(a[1]), "r"(a[2]), "r"(a[3]), "r"(b0), "r"(b1));
}
__device__ __forceinline__ void split2(float v, f16& h, f16& l) {
    h = __float2half_rn(v);
    l = __float2half_rn(v - __half2float(h));
}

// ============= HMMA fp16 GEMM: C = (Ah[+Al]) @ B^T  (2-stage cp.async) =============
// QKV_EPI: epilogue routes (column + cAdd) into per-head Q (scaled+split), K (f16), V (fp32 + f16^T).
template<bool A_SINGLE, int BM, int BN, int SPLITK,
         bool HAS_BIAS, bool HAS_R, bool OUT_SPLIT, bool OUT_T, bool QKV_EPI = false>
__global__ void __launch_bounds__(256) tgemm_kernel(
    int Kk, int lda, int ldb, long long sA, long long sB,
    const f16* __restrict__ Ah, const f16* __restrict__ Al,
    const f16* __restrict__ Bs,
    float* __restrict__ C, int ldc, long long sC, long long sCk,
    f16* __restrict__ Ch, f16* __restrict__ Cl,
    f16* __restrict__ CT, int ldcs, long long sCs,
    const float* __restrict__ bias,
    const float* __restrict__ R, int ldr, long long sR,
    float cMul, float cDiag, float cR,
    float* __restrict__ Kf, float* __restrict__ Vf,
    f16* __restrict__ vT, int cAdd)
{
    constexpr int ASZ = A_SINGLE ? 1 : 2;
    constexpr int MT = BM / 32;
    constexpr int WN = BN / 32;
    constexpr int NG = WN / 2 > 0 ? WN / 2 : 1;
    constexpr int STAGE = ASZ * BM * 128 + BN * 128;
    extern __shared__ char smem[];
    const uint32_t sbase = smem_u32(smem);
    const int tid  = threadIdx.x;
    const int lane = tid & 31, wid = tid >> 5;
    const int wm = wid & 1, wn = wid >> 1;
    const int bz = blockIdx.z;
    const int ks  = (SPLITK > 1) ? (int)(blockIdx.y % SPLITK) : 0;
    const int myT = (SPLITK > 1) ? (int)(blockIdx.y / SPLITK) : (int)blockIdx.y;
    const int rowBlk = myT * BM, colBlk = blockIdx.x * BN;

    const f16* aSrc[2] = {
        Ah + bz * sA + (long long)rowBlk * lda + (long long)ks * Kk,
        A_SINGLE ? nullptr
                 : Al + bz * sA + (long long)rowBlk * lda + (long long)ks * Kk };
    const f16* bSrc = Bs + bz * sB + (long long)colBlk * ldb + (long long)ks * Kk;
    C += bz * sC + (long long)ks * sCk;

    const int r_ld = tid >> 3;
    const int c_ld = tid & 7;

    auto load_stage = [&](int kc, int st) {
        const uint32_t dst0 = sbase + st * STAGE;
        const long long k0 = (long long)kc * 64;
#pragma unroll
        for (int m = 0; m < ASZ; m++) {
            const f16* S = aSrc[m] + k0;
            const uint32_t mb = dst0 + m * (BM * 128);
#pragma unroll
            for (int j = 0; j < BM / 32; j++) {
                int r = r_ld + 32 * j;
                cpasync16(mb + r * 128 + ((c_ld ^ (r & 7)) << 4),
                          S + (long long)r * lda + c_ld * 8);
            }
        }
        {
            const f16* S = bSrc + k0;
            const uint32_t mb = dst0 + ASZ * BM * 128;
#pragma unroll
            for (int j = 0; j < BN / 32; j++) {
                int r = r_ld + 32 * j;
                cpasync16(mb + r * 128 + ((c_ld ^ (r & 7)) << 4),
                          S + (long long)r * ldb + c_ld * 8);
            }
        }
        cp_commit();
    };

    float acc[MT][WN][4] = {};
    const int nch = Kk >> 6;
    load_stage(0, 0);
    if (nch > 1) load_stage(1, 1);

    for (int ci = 0; ci < nch; ci++) {
        if (ci + 1 < nch) { asm volatile("cp.async.wait_group 1;"); }
        else              { asm volatile("cp.async.wait_group 0;"); }
        __syncthreads();

        const uint32_t st = sbase + (ci & 1) * STAGE;
        const uint32_t Ah_b = st, Al_b = st + BM * 128, B_b = st + ASZ * BM * 128;

#pragma unroll
        for (int kss = 0; kss < 4; kss++) {
            const int c = kss * 2 + (lane >> 4);
            uint32_t ah[MT][4], al[MT][4], bs[NG][4];
#pragma unroll
            for (int mt = 0; mt < MT; mt++) {
                int r = wm * (BM / 2) + mt * 16 + (lane & 15);
                uint32_t off = r * 128 + ((c ^ (r & 7)) << 4);
                ldsm4(ah[mt], Ah_b + off);
                if (!A_SINGLE) ldsm4(al[mt], Al_b + off);
            }
#pragma unroll
            for (int ng = 0; ng < NG; ng++) {
                int r = wn * (WN * 8) + ng * 16 + (lane & 15);
                uint32_t off = r * 128 + ((c ^ (r & 7)) << 4);
                ldsm4(bs[ng], B_b + off);
            }
#pragma unroll
            for (int mt = 0; mt < MT; mt++)
#pragma unroll
                for (int nt = 0; nt < WN; nt++) {
                    const int ng = nt >> 1, hb = nt & 1;
                    mma16816(acc[mt][nt], ah[mt], bs[ng][hb], bs[ng][hb + 2]);
                    if (!A_SINGLE)
                        mma16816(acc[mt][nt], al[mt], bs[ng][hb], bs[ng][hb + 2]);
                }
        }
        __syncthreads();
        if (ci + 2 < nch) load_stage(ci + 2, ci & 1);
    }

    // epilogue
#pragma unroll
    for (int mt = 0; mt < MT; mt++) {
        const int r0 = rowBlk + wm * (BM / 2) + mt * 16 + (lane >> 2);
#pragma unroll
        for (int nt = 0; nt < WN; nt++) {
            const int c0 = colBlk + wn * (WN * 8) + nt * 8 + (lane & 3) * 2;
            float2 v0 = make_float2(acc[mt][nt][0] * cMul, acc[mt][nt][1] * cMul);
            float2 v1 = make_float2(acc[mt][nt][2] * cMul, acc[mt][nt][3] * cMul);
            if (QKV_EPI) {
                // route global column cq in [0,1536): sec 0=Q,1=K,2=V; per-head [h][NT][64]
                const int cq = c0 + cAdd;
                const int sec = cq >> 9;
                const int hh_ = (cq >> 6) & 7;
                const int cc = cq & 63;
                const long long d0 = (((long long)hh_ * NT) + r0) * 64 + cc;
                const long long d1 = (((long long)hh_ * NT) + r0 + 8) * 64 + cc;
                if (sec == 0) {
                    v0.x *= 0.125f; v0.y *= 0.125f; v1.x *= 0.125f; v1.y *= 0.125f;
                    *(float2*)(C + d0) = v0;
                    *(float2*)(C + d1) = v1;
                    f16 h00, l00, h01, l01, h10, l10, h11, l11;
                    split2(v0.x, h00, l00); split2(v0.y, h01, l01);
                    split2(v1.x, h10, l10); split2(v1.y, h11, l11);
                    *(__half2*)(Ch + d0) = __half2(h00, h01);
                    *(__half2*)(Cl + d0) = __half2(l00, l01);
                    *(__half2*)(Ch + d1) = __half2(h10, h11);
                    *(__half2*)(Cl + d1) = __half2(l10, l11);
                } else if (sec == 1) {
                    *(float2*)(Kf + d0) = v0;
                    *(float2*)(Kf + d1) = v1;
                    *(__half2*)(CT + d0) = __half2(__float2half_rn(v0.x), __float2half_rn(v0.y));
                    *(__half2*)(CT + d1) = __half2(__float2half_rn(v1.x), __float2half_rn(v1.y));
                } else {
                    *(float2*)(Vf + d0) = v0;
                    *(float2*)(Vf + d1) = v1;
                    long long t0 = ((long long)hh_ * 64 + cc) * NT + r0;
                    long long t1 = ((long long)hh_ * 64 + cc + 1) * NT + r0;
                    vT[t0]     = __float2half_rn(v0.x);
                    vT[t1]     = __float2half_rn(v0.y);
                    vT[t0 + 8] = __float2half_rn(v1.x);
                    vT[t1 + 8] = __float2half_rn(v1.y);
                }
            } else {
                if (cDiag != 0.f) {
                    if (r0 == c0)         v0.x += cDiag;
                    if (r0 == c0 + 1)     v0.y += cDiag;
                    if (r0 + 8 == c0)     v1.x += cDiag;
                    if (r0 + 8 == c0 + 1) v1.y += cDiag;
                }
                if (HAS_BIAS) {
                    float b0 = bias[c0], b1 = bias[c0 + 1];
                    v0.x += b0; v0.y += b1; v1.x += b0; v1.y += b1;
                }
                if (HAS_R) {
                    const float* rp0 = R + bz * sR + (long long)r0 * ldr + c0;
                    const float* rp1 = R + bz * sR + (long long)(r0 + 8) * ldr + c0;
                    v0.x += cR * rp0[0]; v0.y += cR * rp0[1];
                    v1.x += cR * rp1[0]; v1.y += cR * rp1[1];
                }
                *(float2*)(C + (long long)r0 * ldc + c0) = v0;
                *(float2*)(C + (long long)(r0 + 8) * ldc + c0) = v1;
                if (OUT_SPLIT || OUT_T) {
                    f16 h00, l00, h01, l01, h10, l10, h11, l11;
                    split2(v0.x, h00, l00); split2(v0.y, h01, l01);
                    split2(v1.x, h10, l10); split2(v1.y, h11, l11);
                    if (OUT_SPLIT) {
                        long long b0 = bz * sCs + (long long)r0 * ldcs + c0;
                        long long b1 = bz * sCs + (long long)(r0 + 8) * ldcs + c0;
                        *(__half2*)(Ch + b0) = __half2(h00, h01);
                        *(__half2*)(Cl + b0) = __half2(l00, l01);
                        *(__half2*)(Ch + b1) = __half2(h10, h11);
                        *(__half2*)(Cl + b1) = __half2(l10, l11);
                    }
                    if (OUT_T) {
                        long long t00 = bz * sCs + (long long)c0 * ldcs + r0;
                        long long t01 = bz * sCs + (long long)(c0 + 1) * ldcs + r0;
                        CT[t00] = h00;      CT[t01] = h01;
                        CT[t00 + 8] = h10;  CT[t01 + 8] = h11;
                    }
                }
            }
        }
    }
}

template<bool A_SINGLE, int BM, int BN, int SPLITK,
         bool HAS_BIAS, bool HAS_R, bool OUT_SPLIT, bool OUT_T, bool QKV_EPI = false>
void launch_tg(cudaStream_t stm, int Mm, int Nn, int Kslice, int lda, int ldb,
               long long sA, long long sB,
               const f16* Ah, const f16* Al, const f16* Bs,
               float* C, int ldc, long long sC, long long sCk, int batch,
               f16* Ch = nullptr, f16* Cl = nullptr, f16* CT = nullptr,
               int ldcs = 0, long long sCs = 0,
               const float* bias = nullptr,
               const float* R = nullptr, int ldr = 0, long long sR = 0,
               float cMul = 1.f, float cDiag = 0.f, float cR = 0.f,
               float* Kf = nullptr, float* Vf = nullptr, f16* vT = nullptr,
               int cAdd = 0)
{
    constexpr int ASZ = A_SINGLE ? 1 : 2;
    constexpr int SM = 2 * (ASZ * BM * 128 + BN * 128);
    static bool done = false;
    if (!done) {
        cudaFuncSetAttribute(
            tgemm_kernel<A_SINGLE, BM, BN, SPLITK, HAS_BIAS, HAS_R, OUT_SPLIT, OUT_T, QKV_EPI>,
            cudaFuncAttributeMaxDynamicSharedMemorySize, SM);
        done = true;
    }
    dim3 grid(Nn / BN, (Mm / BM) * SPLITK, batch);
    tgemm_kernel<A_SINGLE, BM, BN, SPLITK, HAS_BIAS, HAS_R, OUT_SPLIT, OUT_T, QKV_EPI>
        <<<grid, 256, SM, stm>>>(
        Kslice, lda, ldb, sA, sB, Ah, Al, Bs, C, ldc, sC, sCk,
        Ch, Cl, CT, ldcs, sCs, bias, R, ldr, sR, cMul, cDiag, cR, Kf, Vf, vT, cAdd);
}

// ---------------- split / transpose ----------------
__global__ void split_kernel(const float* __restrict__ x,
                             f16* __restrict__ h, f16* __restrict__ l, int n4)
{
    int i = blockIdx.x * 256 + threadIdx.x;
    if (i >= n4) return;
    float4 v = ((const float4*)x)[i];
    f16 h0, l0, h1, l1, h2, l2, h3, l3;
    split2(v.x, h0, l0); split2(v.y, h1, l1);
    split2(v.z, h2, l2); split2(v.w, h3, l3);
    __half2* hp = (__half2*)h;
    __half2* lp = (__half2*)l;
    hp[i * 2 + 0] = __half2(h0, h1);
    hp[i * 2 + 1] = __half2(h2, h3);
    lp[i * 2 + 0] = __half2(l0, l1);
    lp[i * 2 + 1] = __half2(l2, l3);
}

// W[K][N] fp32 (batched) -> T [N][K] fp16 single
__global__ void tsplit_kernel(const float* __restrict__ W, int Kk, int Nn,
                              f16* __restrict__ T, long long sIn, long long sOut)
{
    __shared__ float tile[32][33];
    const float* Wb = W + blockIdx.z * sIn;
    int n0 = blockIdx.x * 32, k0 = blockIdx.y * 32;
    int x = threadIdx.x, y = threadIdx.y;
    for (int i = y; i < 32; i += 8)
        tile[i][x] = Wb[(long long)(k0 + i) * Nn + n0 + x];
    __syncthreads();
    for (int i = y; i < 32; i += 8) {
        long long o = blockIdx.z * sOut + (long long)(n0 + i) * Kk + k0 + x;
        T[o] = __float2half_rn(tile[x][i]);
    }
}

// ---------------- SIMT tiled SGEMM (t2v only) ----------------
template<int BM, int BN, int BK, int TM, int TN>
__global__ void sgemm_kernel(
    int Kk,
    const float* __restrict__ A, int lda, long long sA,
    const float* __restrict__ B, int ldb, long long sB,
    float* __restrict__ C, int ldc, long long sC)
{
    constexpr int THREADS = (BM / TM) * (BN / TN);
    __shared__ float As[BK][BM];
    __shared__ float Bsm[BK][BN];
    const int tid = threadIdx.x, bz = blockIdx.z;
    A += (long long)bz * sA; B += (long long)bz * sB; C += (long long)bz * sC;
    const int rowBlk = blockIdx.y * BM, colBlk = blockIdx.x * BN;
    constexpr int A_LOADS = (BM * BK) / (4 * THREADS);
    constexpr int B_LOADS = (BK * BN) / (4 * THREADS);
    const int tcol = tid % (BN / TN), trow = tid / (BN / TN);
    float acc[TM][TN] = {};
    for (int k0 = 0; k0 < Kk; k0 += BK) {
#pragma unroll
        for (int l = 0; l < A_LOADS; l++) {
            int idx = tid + l * THREADS;
            int ar = idx / (BK / 4), ac = (idx % (BK / 4)) * 4;
            float4 v = *(const float4*)(A + (long long)(rowBlk + ar) * lda + k0 + ac);
            As[ac + 0][ar] = v.x; As[ac + 1][ar] = v.y;
            As[ac + 2][ar] = v.z; As[ac + 3][ar] = v.w;
        }
#pragma unroll
        for (int l = 0; l < B_LOADS; l++) {
            int idx = tid + l * THREADS;
            int br = idx / (BN / 4), bc = (idx % (BN / 4)) * 4;
            *(float4*)&Bsm[br][bc] = *(const float4*)(B + (long long)(k0 + br) * ldb + colBlk + bc);
        }
        __syncthreads();
#pragma unroll
        for (int k = 0; k < BK; k++) {
            float ar[TM], br[TN];
#pragma unroll
            for (int i = 0; i < TM; i++) ar[i] = As[k][trow * TM + i];
#pragma unroll
            for (int j = 0; j < TN; j++) br[j] = Bsm[k][tcol * TN + j];
#pragma unroll
            for (int i = 0; i < TM; i++)
#pragma unroll
                for (int j = 0; j < TN; j++) acc[i][j] += ar[i] * br[j];
        }
        __syncthreads();
    }
#pragma unroll
    for (int i = 0; i < TM; i++)
#pragma unroll
        for (int j = 0; j < TN; j++)
            C[(long long)(rowBlk + trow * TM + i) * ldc + colBlk + tcol * TN + j] = acc[i][j];
}

// ---------------- pipeline helpers ----------------
__global__ void landmarks_kernel(const float* __restrict__ Qh,
                                 const float* __restrict__ Kh,
                                 f16* __restrict__ qlh, f16* __restrict__ qll,
                                 f16* __restrict__ klm)
{
    int h = blockIdx.y, mi = blockIdx.x, c = threadIdx.x;  // 64 threads
    const float* qb = Qh + (((long long)h * NT) + mi * 32) * DHd + c;
    const float* kb = Kh + (((long long)h * NT) + mi * 32) * DHd + c;
    float qs = 0.f, ks = 0.f;
#pragma unroll
    for (int t = 0; t < 32; t++) { qs += qb[t * DHd]; ks += kb[t * DHd]; }
    qs *= (1.f / 32.f); ks *= (1.f / 32.f);
    long long o = ((long long)h * LM + mi) * DHd + c;
    f16 hh, ll;
    split2(qs, hh, ll); qlh[o] = hh; qll[o] = ll;
    klm[o] = __float2half_rn(ks);
}

// warp-per-row softmax for 256-column rows; writes fp16 splits (+fp32 if WF32)
template<bool WF32>
__global__ void softmax256_kernel(float* __restrict__ x,
                                  f16* __restrict__ oh, f16* __restrict__ ol)
{
    long long row = (long long)blockIdx.x * 8 + (threadIdx.x >> 5);
    int lane = threadIdx.x & 31;
    float* p = x + row * 256 + lane * 8;
    float4 a = *(float4*)p;
    float4 b = *(float4*)(p + 4);
    float m = fmaxf(fmaxf(fmaxf(a.x, a.y), fmaxf(a.z, a.w)),
                    fmaxf(fmaxf(b.x, b.y), fmaxf(b.z, b.w)));
#pragma unroll
    for (int o = 16; o; o >>= 1) m = fmaxf(m, __shfl_xor_sync(0xffffffffu, m, o));
    a.x = expf(a.x - m); a.y = expf(a.y - m); a.z = expf(a.z - m); a.w = expf(a.w - m);
    b.x = expf(b.x - m); b.y = expf(b.y - m); b.z = expf(b.z - m); b.w = expf(b.w - m);
    float s = a.x + a.y + a.z + a.w + b.x + b.y + b.z + b.w;
#pragma unroll
    for (int o = 16; o; o >>= 1) s += __shfl_xor_sync(0xffffffffu, s, o);
    float inv = 1.f / s;
    a.x *= inv; a.y *= inv; a.z *= inv; a.w *= inv;
    b.x *= inv; b.y *= inv; b.z *= inv; b.w *= inv;
    if (WF32) { *(float4*)p = a; *(float4*)(p + 4) = b; }
    float vals[8] = {a.x, a.y, a.z, a.w, b.x, b.y, b.z, b.w};
    __half2* ph = (__half2*)(oh + row * 256 + lane * 8);
    __half2* pl = (__half2*)(ol + row * 256 + lane * 8);
#pragma unroll
    for (int q = 0; q < 4; q++) {
        f16 h0, l0, h1, l1;
        split2(vals[q * 2], h0, l0); split2(vals[q * 2 + 1], h1, l1);
        ph[q] = __half2(h0, h1);
        pl[q] = __half2(l0, l1);
    }
}

// block-per-row softmax for 8192-column rows, register-resident; splits only
__global__ void softmax_wide_kernel(const float* __restrict__ x,
                                    f16* __restrict__ oh, f16* __restrict__ ol)
{
    long long row = blockIdx.x;
    const float* p = x + row * NT;
    int t = threadIdx.x, w = t >> 5, lane = t & 31;
    __shared__ float red[8];
    float v[32];
    float m = -1e30f;
#pragma unroll
    for (int i = 0; i < 32; i++) { v[i] = p[i * 256 + t]; m = fmaxf(m, v[i]); }
#pragma unroll
    for (int o = 16; o; o >>= 1) m = fmaxf(m, __shfl_xor_sync(0xffffffffu, m, o));
    if (!lane) red[w] = m;
    __syncthreads();
    m = red[0];
#pragma unroll
    for (int i = 1; i < 8; i++) m = fmaxf(m, red[i]);
    __syncthreads();
    float s = 0.f;
#pragma unroll
    for (int i = 0; i < 32; i++) { v[i] = expf(v[i] - m); s += v[i]; }
#pragma unroll
    for (int o = 16; o; o >>= 1) s += __shfl_xor_sync(0xffffffffu, s, o);
    if (!lane) red[w] = s;
    __syncthreads();
    s = red[0];
#pragma unroll
    for (int i = 1; i < 8; i++) s += red[i];
    float inv = 1.f / s;
    f16* ph = oh + row * NT + t;
    f16* pl = ol + row * NT + t;
#pragma unroll
    for (int i = 0; i < 32; i++) {
        f16 hh, ll; split2(v[i] * inv, hh, ll);
        ph[i * 256] = hh; pl[i * 256] = ll;
    }
}

__global__ void zero_kernel(float* p, int n)
{
    int i = blockIdx.x * blockDim.x + threadIdx.x;
    if (i < n) p[i] = 0.f;
}

__device__ __forceinline__ void atomicMaxPos(float* addr, float v)
{
    atomicMax((int*)addr, __float_as_int(v));
}

__global__ void attn2_scale_kernel(const float* __restrict__ a2, float* __restrict__ mx)
{
    int h = blockIdx.x, t = threadIdx.x;
    const float* p = a2 + (long long)h * LM * LM;
    float cs = 0.f, rs = 0.f;
    for (int i = 0; i < LM; i++) cs += fabsf(p[i * LM + t]);
    for (int j = 0; j < LM; j++) rs += fabsf(p[t * LM + j]);
    __shared__ float r1[256], r2[256];
    r1[t] = cs; r2[t] = rs; __syncthreads();
    for (int s = 128; s; s >>= 1) {
        if (t < s) { r1[t] = fmaxf(r1[t], r1[t + s]); r2[t] = fmaxf(r2[t], r2[t + s]); }
        __syncthreads();
    }
    if (!t) { atomicMaxPos(&mx[0], r2[0]); atomicMaxPos(&mx[1], r1[0]); }
}

__global__ void pinv_init_kernel(const float* __restrict__ a2, float* __restrict__ z,
                                 f16* __restrict__ zh, f16* __restrict__ zl,
                                 f16* __restrict__ zT, const float* __restrict__ mx)
{
    int idx = blockIdx.x * blockDim.x + threadIdx.x;  // H*LM*LM
    float inv = 1.f / (mx[0] * mx[1]);
    int h = idx >> 16, r = (idx >> 8) & 255, c = idx & 255;
    int tidx = (h << 16) + (c << 8) + r;
    float v = a2[tidx] * inv;
    z[idx] = v;
    f16 hh, ll; split2(v, hh, ll);
    zh[idx] = hh; zl[idx] = ll;
    zT[tidx] = hh;
}

__global__ void reduce_t3v_kernel(const float* __restrict__ part, float* __restrict__ out)
{
    int idx = blockIdx.x * blockDim.x + threadIdx.x;  // H*LM*DHd
    int h = idx / (LM * DHd), rc = idx % (LM * DHd);
    const float* p = part + (long long)h * 8 * LM * DHd + rc;
    float s = 0.f;
#pragma unroll
    for (int q = 0; q < 8; q++) s += p[(long long)q * LM * DHd];
    out[idx] = s;
}

__global__ void conv_res_kernel(float* __restrict__ conv, const float* __restrict__ Vh,
                                const float* __restrict__ cw)
{
    int idx = blockIdx.x * blockDim.x + threadIdx.x;  // NT*IN
    int i = idx / IN, hc = idx % IN;
    int h = hc >> 6, c = hc & 63;
    const float* vb = Vh + ((long long)h * NT) * DHd + c;
    float s = 0.f;
#pragma unroll
    for (int k = 0; k < CK; k++) {
        int j = i + k - CK / 2;
        if (j >= 0 && j < NT) s += cw[h * CK + k] * vb[(long long)j * DHd];
    }
    conv[idx] = s;
}

__global__ void edge_kernel(const int* __restrict__ rows, const int* __restrict__ cols,
                            const float* __restrict__ vals,
                            const float* __restrict__ qk,
                            float* __restrict__ Araw, int E)
{
    int e = blockIdx.x * (blockDim.x / 32) + threadIdx.x / 32;
    int lane = threadIdx.x & 31;
    if (e >= E) return;
    int r = rows[e], c = cols[e];
    const float4* qr = (const float4*)(qk + (long long)r * (2 * WQ));
    const float4* kr = (const float4*)(qk + (long long)c * (2 * WQ) + WQ);
    float s = 0.f;
#pragma unroll
    for (int t = lane; t < WQ / 4; t += 32) {
        float4 a = qr[t], b = kr[t];
        s += a.x * b.x + a.y * b.y + a.z * b.z + a.w * b.w;
    }
#pragma unroll
    for (int o = 16; o; o >>= 1) s += __shfl_xor_sync(0xffffffffu, s, o);
    if (!lane) atomicAdd(&Araw[r], vals[e] * s * 0.0625f);
}

__global__ void alpha_kernel(const float* __restrict__ Araw, float* __restrict__ alpha,
                             float* __restrict__ out_tail)
{
    __shared__ float red[1024];
    int t = threadIdx.x;
    float m = -1e30f;
    for (int i = t; i < NT; i += 1024) m = fmaxf(m, Araw[i]);
    red[t] = m; __syncthreads();
    for (int s = 512; s; s >>= 1) { if (t < s) red[t] = fmaxf(red[t], red[t + s]); __syncthreads(); }
    m = red[0]; __syncthreads();
    float sum = 0.f;
    for (int i = t; i < NT; i += 1024) sum += expf(Araw[i] - m);
    red[t] = sum; __syncthreads();
    for (int s = 512; s; s >>= 1) { if (t < s) red[t] += red[t + s]; __syncthreads(); }
    float inv = 1.f / red[0];
    for (int i = t; i < NT; i += 1024) {
        alpha[i] = expf(Araw[i] - m) * inv;
        if (out_tail) out_tail[i] = Araw[i];
    }
}

__global__ void final_kernel(const float* __restrict__ value, const float* __restrict__ enc,
                             const float* __restrict__ alpha, float* __restrict__ out)
{
    long long idx = (long long)blockIdx.x * blockDim.x + threadIdx.x;  // NT*D
    int i = (int)(idx / D);
    float xl = alpha[i] * value[idx];
    float w  = 1.f / (1.f + expf(xl));
    float sw = w * w;
    out[idx] = 2.f * xl * sw + 2.f * enc[idx] * (1.f - sw);
}

template <typename T, size_t N>
T* sym(const T (&s)[N])
{
    void* p = nullptr;
    cudaGetSymbolAddress(&p, s);
    return (T*)p;
}

} // namespace

extern "C" void kernel_launch(void* const* d_in, const int* in_sizes, int n_in,
                              void* d_out, int out_size)
{
    const float* dense    = (const float*)d_in[0];
    const int*   adj_rows = (const int*)d_in[1];
    const int*   adj_cols = (const int*)d_in[2];
    const float* adj_vals = (const float*)d_in[3];
    const float* wq       = (const float*)d_in[4];
    const float* wk       = (const float*)d_in[5];
    const float* wv_w     = (const float*)d_in[6];
    const float* wv_b     = (const float*)d_in[7];
    const float* qkv_w    = (const float*)d_in[8];
    const float* out_w    = (const float*)d_in[9];
    const float* out_b    = (const float*)d_in[10];
    const float* conv_w   = (const float*)d_in[11];
    float*       out      = (float*)d_out;
    const int E = in_sizes[1];

    static cudaStream_t s1 = nullptr, s2 = nullptr, s3 = nullptr;
    static cudaEvent_t evStart = nullptr, evDense = nullptr, evFork = nullptr,
                       evPinv = nullptr, evVal = nullptr, evLand = nullptr,
                       evA1 = nullptr, evV = nullptr, evConv = nullptr,
                       evW = nullptr;
    if (!s1) {
        cudaStreamCreateWithFlags(&s1, cudaStreamNonBlocking);
        cudaStreamCreateWithFlags(&s2, cudaStreamNonBlocking);
        cudaStreamCreateWithFlags(&s3, cudaStreamNonBlocking);
        cudaEventCreateWithFlags(&evStart, cudaEventDisableTiming);
        cudaEventCreateWithFlags(&evDense, cudaEventDisableTiming);
        cudaEventCreateWithFlags(&evFork, cudaEventDisableTiming);
        cudaEventCreateWithFlags(&evPinv, cudaEventDisableTiming);
        cudaEventCreateWithFlags(&evVal, cudaEventDisableTiming);
        cudaEventCreateWithFlags(&evLand, cudaEventDisableTiming);
        cudaEventCreateWithFlags(&evA1, cudaEventDisableTiming);
        cudaEventCreateWithFlags(&evV, cudaEventDisableTiming);
        cudaEventCreateWithFlags(&evConv, cudaEventDisableTiming);
        cudaEventCreateWithFlags(&evW, cudaEventDisableTiming);
    }
    cudaStream_t s0 = 0;

    float* Qh    = sym(g_Qh);     float* Kh    = sym(g_Kh);
    float* Vh    = sym(g_Vh);
    float* attn1 = sym(g_attn1);  float* attn3 = sym(g_attn3);
    float* attn2 = sym(g_attn2);  float* xz    = sym(g_xz);
    float* t1    = sym(g_t1);     float* t2    = sym(g_t2);
    float* zA    = sym(g_z);      float* zB    = sym(g_z2);
    float* t3vp  = sym(g_t3vp);   float* t3v   = sym(g_t3v);
    float* t2v   = sym(g_t2v);    float* conv  = sym(g_conv);
    float* OH    = sym(g_OH);     float* enc   = sym(g_enc);
    float* q2k2  = sym(g_q2k2);   float* val   = sym(g_val);
    float* Araw  = sym(g_Araw);   float* alphaB= sym(g_alpha);
    float* mx2   = sym(g_max2);

    f16* dense_h = sym(g_dense_h); f16* dense_l = sym(g_dense_l);
    f16* enc_h   = sym(g_enc_h);   f16* enc_l   = sym(g_enc_l);
    f16* OH_h    = sym(g_OH_h);    f16* OH_l    = sym(g_OH_l);
    f16* wqkvT   = sym(g_wqkvT);   f16* wvT     = sym(g_wvT);
    f16* woutT   = sym(g_woutT);   f16* wqkT    = sym(g_wqkT);
    f16* Qh_h = sym(g_Qh_h); f16* Qh_l = sym(g_Qh_l);
    f16* KhB = sym(g_KhB);   f16* VhT = sym(g_VhT);
    f16* qlm_h = sym(g_qlm_h); f16* qlm_l = sym(g_qlm_l);
    f16* klm = sym(g_klm);
    f16* a1h = sym(g_a1h); f16* a1l = sym(g_a1l);
    f16* a3h = sym(g_a3h); f16* a3l = sym(g_a3l);
    f16* a2h = sym(g_a2h); f16* a2l = sym(g_a2l);
    f16* zh_a = sym(g_zh_a); f16* zl_a = sym(g_zl_a); f16* zT_a = sym(g_zT_a);
    f16* zh_b = sym(g_zh_b); f16* zl_b = sym(g_zl_b); f16* zT_b = sym(g_zT_b);
    f16* xzh = sym(g_xzh); f16* xzl = sym(g_xzl); f16* xzT = sym(g_xzT);
    f16* t2T = sym(g_t2T); f16* t1T = sym(g_t1T);
    f16* t2vT = sym(g_t2vT);

    const long long SLM = (long long)LM * LM;
    const long long SH64 = (long long)NT * DHd;

    // ---- fork side streams from capture origin FIRST ----
    cudaEventRecord(evStart, s0);

    // ---- s3: zero Araw + weight transposes (forked; joined where consumed) ----
    cudaStreamWaitEvent(s3, evStart, 0);
    zero_kernel<<<NT / 256, 256, 0, s3>>>(Araw, NT);
    { dim3 b(32, 8);
      tsplit_kernel<<<dim3(3 * IN / 32, D / 32, 1), b, 0, s3>>>(qkv_w, D, 3 * IN, wqkvT, 0, 0);
      tsplit_kernel<<<dim3(D / 32, D / 32, 1), b, 0, s3>>>(wv_w, D, D, wvT, 0, 0);
      tsplit_kernel<<<dim3(D / 32, IN / 32, 1), b, 0, s3>>>(out_w, IN, D, woutT, 0, 0);
      tsplit_kernel<<<dim3(WQ / 32, D / 32, 1), b, 0, s3>>>(wq, D, WQ, wqkT, 0, 0);
      tsplit_kernel<<<dim3(WQ / 32, D / 32, 1), b, 0, s3>>>(wk, D, WQ, wqkT + (long long)WQ * D, 0, 0);
    }
    cudaEventRecord(evW, s3);

    // ---- s0: activation split ----
    split_kernel<<<NT * D / 4 / 256, 256>>>(dense, dense_h, dense_l, NT * D / 4);
    cudaEventRecord(evDense, s0);

    // join weights into s0 before any weight-consuming GEMM
    cudaStreamWaitEvent(s0, evW, 0);

    // ---- s2: V GEMM (cols [1024,1536)) -> Vh + VhT, then conv, then val ----
    cudaStreamWaitEvent(s2, evDense, 0);
    cudaStreamWaitEvent(s2, evW, 0);
    launch_tg<false,128,128,1,false,false,false,false,true>(s2, NT, IN, D, D, D, 0, 0,
        dense_h, dense_l, wqkvT + (long long)2 * IN * D, Qh, 0, 0, 0, 1,
        Qh_h, Qh_l, KhB, 0, 0,
        nullptr, nullptr, 0, 0, 1.f, 0.f, 0.f,
        Kh, Vh, VhT, 2 * IN);
    cudaEventRecord(evV, s2);
    conv_res_kernel<<<NT * IN / 256, 256, 0, s2>>>(conv, Vh, conv_w);
    cudaEventRecord(evConv, s2);
    launch_tg<true,128,128,1,true,false,false,false>(s2, NT, D, D, D, D, 0, 0,
        dense_h, nullptr, wvT, val, D, 0, 0, 1,
        nullptr, nullptr, nullptr, 0, 0, wv_b);
    cudaEventRecord(evVal, s2);

    // ---- s0: QK GEMM (cols [0,1024)) -> Qh fp32/splits + Kh fp32 + KhB f16 ----
    launch_tg<false,128,128,1,false,false,false,false,true>(s0, NT, 2 * IN, D, D, D, 0, 0,
        dense_h, dense_l, wqkvT, Qh, 0, 0, 0, 1,
        Qh_h, Qh_l, KhB, 0, 0,
        nullptr, nullptr, 0, 0, 1.f, 0.f, 0.f,
        Kh, Vh, VhT, 0);

    { dim3 g(LM, H); landmarks_kernel<<<g, DHd>>>(Qh, Kh, qlm_h, qlm_l, klm); }
    cudaEventRecord(evLand, s0);

    // ---- s3: attn1 logits + softmax ----
    cudaStreamWaitEvent(s3, evLand, 0);
    launch_tg<false,128,128,1,false,false,false,false>(s3, NT, LM, DHd, DHd, DHd,
        SH64, (long long)LM * DHd,
        Qh_h, Qh_l, klm, attn1, LM, (long long)NT * LM, 0, H);
    softmax256_kernel<false><<<H * NT / 8, 256, 0, s3>>>(attn1, a1h, a1l);
    cudaEventRecord(evA1, s3);

    // attn2 logits + fused softmax/split
    launch_tg<false,64,64,1,false,false,false,false>(s0, LM, LM, DHd, DHd, DHd,
        (long long)LM * DHd, (long long)LM * DHd,
        qlm_h, qlm_l, klm, attn2, LM, SLM, 0, H);
    softmax256_kernel<true><<<H * LM / 8, 256>>>(attn2, a2h, a2l);
    cudaEventRecord(evFork, s0);

    // ---- s1: pinv chain (64x64 tiles -> 128 CTAs per GEMM) ----
    cudaStreamWaitEvent(s1, evFork, 0);
    zero_kernel<<<1, 32, 0, s1>>>(mx2, 2);
    attn2_scale_kernel<<<H, 256, 0, s1>>>(attn2, mx2);
    pinv_init_kernel<<<H * LM * LM / 256, 256, 0, s1>>>(attn2, zA, zh_a, zl_a, zT_a, mx2);
    {
        f16 *zh = zh_a, *zl = zl_a, *zT = zT_a;
        f16 *nzh = zh_b, *nzl = zl_b, *nzT = zT_b;
        for (int it = 0; it < 6; it++) {
            launch_tg<false,64,64,1,false,false,true,true>(s1, LM, LM, LM, LM, LM, SLM, SLM,
                a2h, a2l, zT, xz, LM, SLM, 0, H,
                xzh, xzl, xzT, LM, SLM);
            launch_tg<false,64,64,1,false,true,false,true>(s1, LM, LM, LM, LM, LM, SLM, SLM,
                xzh, xzl, xzT, t2, LM, SLM, 0, H,
                nullptr, nullptr, t2T, LM, SLM,
                nullptr, xz, LM, SLM, 1.f, 15.f, -7.f);
            launch_tg<false,64,64,1,false,false,false,true>(s1, LM, LM, LM, LM, LM, SLM, SLM,
                xzh, xzl, t2T, t1, LM, SLM, 0, H,
                nullptr, nullptr, t1T, LM, SLM,
                nullptr, nullptr, 0, 0, -1.f, 13.f, 0.f);
            launch_tg<false,64,64,1,false,false,true,true>(s1, LM, LM, LM, LM, LM, SLM, SLM,
                zh, zl, t1T, zB, LM, SLM, 0, H,
                nzh, nzl, nzT, LM, SLM,
                nullptr, nullptr, 0, 0, 0.25f, 0.f, 0.f);
            { float* tf = zA; zA = zB; zB = tf; }
            { f16* tb;
              tb = zh; zh = nzh; nzh = tb;
              tb = zl; zl = nzl; nzl = tb;
              tb = zT; zT = nzT; nzT = tb; }
        }
    }
    cudaEventRecord(evPinv, s1);

    // ---- s0: attn3 logits + softmax, t3v ----
    launch_tg<false,128,128,1,false,false,false,false>(s0, LM, NT, DHd, DHd, DHd,
        (long long)LM * DHd, SH64,
        qlm_h, qlm_l, KhB, attn3, NT, (long long)LM * NT, 0, H);
    softmax_wide_kernel<<<H * LM, 256>>>(attn3, a3h, a3l);

    // t3v needs VhT (s2)
    cudaStreamWaitEvent(s0, evV, 0);
    launch_tg<false,64,64,8,false,false,false,false>(s0, LM, DHd, NT / 8, NT, NT,
        (long long)LM * NT, (long long)DHd * NT,
        a3h, a3l, VhT, t3vp, DHd, 8LL * LM * DHd, (long long)LM * DHd, H);
    reduce_t3v_kernel<<<H * LM * DHd / 256, 256>>>(t3vp, t3v);

    cudaStreamWaitEvent(s0, evPinv, 0);

    // t2v = z @ t3v (SIMT, tiny)
    sgemm_kernel<64,64,16,4,4><<<dim3(1, 4, H), 256>>>(LM,
        zA, LM, SLM, t3v, DHd, (long long)LM * DHd, t2v, DHd, (long long)LM * DHd);
    { dim3 b(32, 8);
      tsplit_kernel<<<dim3(DHd / 32, LM / 32, H), b>>>(t2v, LM, DHd,
          t2vT, (long long)LM * DHd, (long long)DHd * LM); }

    // OH = attn1 @ t2v + conv  (fused conv-R, fused split output)
    cudaStreamWaitEvent(s0, evA1, 0);
    cudaStreamWaitEvent(s0, evConv, 0);
    launch_tg<false,128,64,1,false,true,true,false>(s0, NT, DHd, LM, LM, LM,
        (long long)NT * LM, (long long)DHd * LM,
        a1h, a1l, t2vT, OH, IN, (long long)DHd, 0, H,
        OH_h, OH_l, nullptr, IN, (long long)DHd,
        nullptr, conv, IN, (long long)DHd, 1.f, 0.f, 1.f);

    // enc = OH @ out_w + out_b + dense  (fused split output)
    launch_tg<false,128,128,1,true,true,true,false>(s0, NT, D, IN, IN, IN, 0, 0,
        OH_h, OH_l, woutT, enc, D, 0, 0, 1,
        enc_h, enc_l, nullptr, D, 0,
        out_b, dense, D, 0, 1.f, 0.f, 1.f);

    // q2|k2 = enc @ [wq|wk]   (single N=512 GEMM)
    launch_tg<false,128,128,1,false,false,false,false>(s0, NT, 2 * WQ, D, D, D, 0, 0,
        enc_h, enc_l, wqkT, q2k2, 2 * WQ, 0, 0, 1);

    // edge accumulation (Araw zero ordered via evW join above)
    cudaStreamWaitEvent(s0, evW, 0);
    edge_kernel<<<(E + 7) / 8, 256>>>(adj_rows, adj_cols, adj_vals, q2k2, Araw, E);

    float* out_tail = (out_size >= NT * D + NT) ? (out + (long long)NT * D) : nullptr;
    alpha_kernel<<<1, 1024>>>(Araw, alphaB, out_tail);

    cudaStreamWaitEvent(s0, evVal, 0);
    final_kernel<<<(int)(((long long)NT * D) / 256), 256>>>(val, enc, alphaB, out);
}